// round 1
// baseline (speedup 1.0000x reference)
#include <cuda_runtime.h>
#include <math.h>

// Problem constants (fixed by setup_inputs)
#define NPTS 8192
#define C    10
#define REC  32      // floats per j-record (128B, padded)
#define JT   128     // j per SMEM chunk
#define TPB  128     // threads per filter block
#define IPT  2       // i per thread
#define IPB  (TPB*IPT)          // 256 i per block
#define ITILES (NPTS/IPB)       // 32
#define JS   16                 // j splits
#define JCHUNK (NPTS/JS)        // 512

// j-record layout (floats):
//  [0..5]  scaled feats paired for f32x2 dot: (g0,g3),(g1,g4),(g2,g5)
//  [6]     n3/64  (squared norm of first 3 scaled dims, /64)
//  [7]     n6     (squared norm of all 6 scaled dims)
//  [8..17] a[c]  = (Ws @ p)[c]
//  [18..27]b[c]  = (Wb @ p)[c]
//  [28..31] pad
__device__ __align__(16) float g_jrec[NPTS * REC];
__device__ float g_partial[JS * C * NPTS];

typedef unsigned long long u64;

static __device__ __forceinline__ u64 pack2(float lo, float hi) {
    u64 r; asm("mov.b64 %0,{%1,%2};" : "=l"(r) : "f"(lo), "f"(hi)); return r;
}
static __device__ __forceinline__ void unpack2(u64 v, float& lo, float& hi) {
    asm("mov.b64 {%0,%1},%2;" : "=f"(lo), "=f"(hi) : "l"(v));
}
static __device__ __forceinline__ u64 fma2(u64 a, u64 b, u64 c) {
    u64 d; asm("fma.rn.f32x2 %0,%1,%2,%3;" : "=l"(d) : "l"(a), "l"(b), "l"(c)); return d;
}
static __device__ __forceinline__ u64 mul2(u64 a, u64 b) {
    u64 d; asm("mul.rn.f32x2 %0,%1,%2;" : "=l"(d) : "l"(a), "l"(b)); return d;
}
static __device__ __forceinline__ float ex2(float x) {
    float r; asm("ex2.approx.ftz.f32 %0,%1;" : "=f"(r) : "f"(x)); return r;
}

// Scale features by sqrt(0.5*log2(e)) so K = 2^(2*dot - n_i - n_j) directly.
__global__ void prep_kernel(const float* __restrict__ feat) {
    int j = blockIdx.x * blockDim.x + threadIdx.x;
    if (j >= NPTS) return;
    const float S = 0.8493218002880190f;  // sqrt(0.5 * log2(e))
    float g[6];
#pragma unroll
    for (int d = 0; d < 6; d++) g[d] = feat[d * NPTS + j] * S;
    float n3 = g[0]*g[0] + g[1]*g[1] + g[2]*g[2];
    float n6 = n3 + g[3]*g[3] + g[4]*g[4] + g[5]*g[5];
    float* r = g_jrec + (size_t)j * REC;
    r[0] = g[0]; r[1] = g[3]; r[2] = g[1]; r[3] = g[4]; r[4] = g[2]; r[5] = g[5];
    r[6] = n3 * (1.0f / 64.0f);
    r[7] = n6;
}

// p = softmax(q, axis=classes); a = Ws@p, b = Wb@p, written into j-records.
__global__ void softmax_ab_kernel(const float* __restrict__ q,
                                  const float* __restrict__ Ws,
                                  const float* __restrict__ Wb) {
    __shared__ float sWs[C * C], sWb[C * C];
    int t = threadIdx.x;
    if (t < C * C) { sWs[t] = Ws[t]; sWb[t] = Wb[t]; }
    __syncthreads();
    int i = blockIdx.x * blockDim.x + t;
    if (i >= NPTS) return;
    float v[C];
    float m = -1e30f;
#pragma unroll
    for (int c = 0; c < C; c++) { v[c] = q[c * NPTS + i]; m = fmaxf(m, v[c]); }
    float s = 0.0f;
#pragma unroll
    for (int c = 0; c < C; c++) { v[c] = __expf(v[c] - m); s += v[c]; }
    float inv = 1.0f / s;
#pragma unroll
    for (int c = 0; c < C; c++) v[c] *= inv;
    float* r = g_jrec + (size_t)i * REC;
#pragma unroll
    for (int c = 0; c < C; c++) {
        float a = 0.0f, b = 0.0f;
#pragma unroll
        for (int cc = 0; cc < C; cc++) {
            a = fmaf(sWs[c * C + cc], v[cc], a);
            b = fmaf(sWb[c * C + cc], v[cc], b);
        }
        r[8 + c]  = a;
        r[18 + c] = b;
    }
}

// Core: for each i, accumulate msg[c] = sum_j ksp(i,j)*a[c,j] + kbl(i,j)*b[c,j]
// over this block's j-split; write per-split partials.
__global__ void __launch_bounds__(TPB) filter_kernel() {
    __shared__ __align__(16) float sj[JT * REC];
    int ib = blockIdx.x;   // i tile
    int js = blockIdx.y;   // j split
    int t  = threadIdx.x;

    int i0 = ib * IPB + t;
    int i1 = i0 + TPB;

    const u64* r0 = (const u64*)(g_jrec + (size_t)i0 * REC);
    const u64* r1 = (const u64*)(g_jrec + (size_t)i1 * REC);
    u64 pi0_0 = r0[0], pi0_1 = r0[1], pi0_2 = r0[2];
    u64 pi1_0 = r1[0], pi1_1 = r1[1], pi1_2 = r1[2];
    float n0l, n0h, n1l, n1h;
    unpack2(r0[3], n0l, n0h);
    unpack2(r1[3], n1l, n1h);
    float mi3_0 = -n0l, mi6_0 = -n0h;
    float mi3_1 = -n1l, mi6_1 = -n1h;

    u64 acc0[5] = {0, 0, 0, 0, 0};
    u64 acc1[5] = {0, 0, 0, 0, 0};

    int jbase = js * JCHUNK;
    for (int ch = 0; ch < JCHUNK / JT; ch++) {
        __syncthreads();
        const float4* src = (const float4*)(g_jrec + (size_t)(jbase + ch * JT) * REC);
        float4* dst = (float4*)sj;
#pragma unroll
        for (int k = 0; k < (JT * REC) / (4 * TPB); k++)
            dst[t + k * TPB] = src[t + k * TPB];
        __syncthreads();

#pragma unroll 2
        for (int jj = 0; jj < JT; jj++) {
            const u64* bj = (const u64*)(sj + jj * REC);
            u64 pj0 = bj[0], pj1 = bj[1], pj2 = bj[2];
            float n3j, n6j;
            unpack2(bj[3], n3j, n6j);

            // ---- i0 ----
            {
                u64 d2 = fma2(pi0_0, pj0, fma2(pi0_1, pj1, mul2(pi0_2, pj2)));
                float dl, dh; unpack2(d2, dl, dh);
                float xsp = fmaf(0.03125f, dl, mi3_0 - n3j);       // (2*dot3 - n3i - n3j)/64
                float xbl = fmaf(2.0f, dl + dh, mi6_0 - n6j);      // 2*dot6 - n6i - n6j
                float ksp = ex2(xsp);
                float kbl = ex2(xbl);
                u64 k2s = pack2(ksp, ksp);
                u64 k2b = pack2(kbl, kbl);
#pragma unroll
                for (int k = 0; k < 5; k++) {
                    acc0[k] = fma2(k2b, bj[9 + k], acc0[k]);
                    acc0[k] = fma2(k2s, bj[4 + k], acc0[k]);
                }
            }
            // ---- i1 ----
            {
                u64 d2 = fma2(pi1_0, pj0, fma2(pi1_1, pj1, mul2(pi1_2, pj2)));
                float dl, dh; unpack2(d2, dl, dh);
                float xsp = fmaf(0.03125f, dl, mi3_1 - n3j);
                float xbl = fmaf(2.0f, dl + dh, mi6_1 - n6j);
                float ksp = ex2(xsp);
                float kbl = ex2(xbl);
                u64 k2s = pack2(ksp, ksp);
                u64 k2b = pack2(kbl, kbl);
#pragma unroll
                for (int k = 0; k < 5; k++) {
                    acc1[k] = fma2(k2b, bj[9 + k], acc1[k]);
                    acc1[k] = fma2(k2s, bj[4 + k], acc1[k]);
                }
            }
        }
    }

    float* P = g_partial + (size_t)js * C * NPTS;
#pragma unroll
    for (int k = 0; k < 5; k++) {
        float lo, hi;
        unpack2(acc0[k], lo, hi);
        P[(2 * k + 0) * NPTS + i0] = lo;
        P[(2 * k + 1) * NPTS + i0] = hi;
        unpack2(acc1[k], lo, hi);
        P[(2 * k + 0) * NPTS + i1] = lo;
        P[(2 * k + 1) * NPTS + i1] = hi;
    }
}

// Sum partials over j-splits, apply compatibility, q = unaries - compat@msg.
__global__ void reduce_kernel(const float* __restrict__ unaries,
                              const float* __restrict__ compat,
                              float* __restrict__ q) {
    __shared__ float sc[C * C];
    int t = threadIdx.x;
    if (t < C * C) sc[t] = compat[t];
    __syncthreads();
    int i = blockIdx.x * blockDim.x + t;
    if (i >= NPTS) return;
    float m[C];
#pragma unroll
    for (int c = 0; c < C; c++) {
        float s = 0.0f;
#pragma unroll
        for (int js = 0; js < JS; js++)
            s += g_partial[((size_t)js * C + c) * NPTS + i];
        m[c] = s;
    }
#pragma unroll
    for (int c = 0; c < C; c++) {
        float acc = unaries[c * NPTS + i];
#pragma unroll
        for (int cc = 0; cc < C; cc++)
            acc = fmaf(-sc[c * C + cc], m[cc], acc);
        q[c * NPTS + i] = acc;
    }
}

extern "C" void kernel_launch(void* const* d_in, const int* in_sizes, int n_in,
                              void* d_out, int out_size) {
    const float* unaries = (const float*)d_in[0];   // [C, N]
    const float* feat    = (const float*)d_in[1];   // [6, N]
    const float* Ws      = (const float*)d_in[2];   // [C, C]
    const float* Wb      = (const float*)d_in[3];   // [C, C]
    const float* compat  = (const float*)d_in[4];   // [C, C]
    float* q = (float*)d_out;                       // [C, N]

    prep_kernel<<<NPTS / 256, 256>>>(feat);
    for (int it = 0; it < 5; it++) {
        softmax_ab_kernel<<<NPTS / 256, 256>>>(it == 0 ? unaries : q, Ws, Wb);
        dim3 grid(ITILES, JS);
        filter_kernel<<<grid, TPB>>>();
        reduce_kernel<<<NPTS / 256, 256>>>(unaries, compat, q);
    }
}

// round 2
// speedup vs baseline: 1.0038x; 1.0038x over previous
#include <cuda_runtime.h>
#include <math.h>

#define NPTS 8192
#define C    10
#define NPHI 84          // monomials |alpha|<=6 in 3 vars

typedef unsigned long long u64;
typedef unsigned int u32;

// Static scratch (allowed: __device__ globals)
__device__ __align__(16) float g_prep[NPTS * 8];          // bilateral scaled feats+halfnorm
__device__ __align__(16) float g_phi[NPHI * NPTS];        // spatial feature map
__device__ __align__(16) u32   g_K[(size_t)NPTS * NPTS / 2];  // bf16x2 bilateral kernel, row j over i
__device__ __align__(16) float g_A[C * NPTS];             // Ws @ p
__device__ __align__(16) float g_B[NPTS * 12];            // (Wb @ p)^T padded to 12
__device__ __align__(16) float g_T[NPHI * 12];            // A @ Phi^T
__device__ __align__(16) float g_partial[32 * C * NPTS];  // bilateral partials per j-split

static __device__ __forceinline__ u64 pack2(float lo, float hi) {
    u64 r; asm("mov.b64 %0,{%1,%2};" : "=l"(r) : "f"(lo), "f"(hi)); return r;
}
static __device__ __forceinline__ void unpack2(u64 v, float& lo, float& hi) {
    asm("mov.b64 {%0,%1},%2;" : "=f"(lo), "=f"(hi) : "l"(v));
}
static __device__ __forceinline__ u64 fma2(u64 a, u64 b, u64 c) {
    u64 d; asm("fma.rn.f32x2 %0,%1,%2,%3;" : "=l"(d) : "l"(a), "l"(b), "l"(c)); return d;
}
static __device__ __forceinline__ u64 mul2(u64 a, u64 b) {
    u64 d; asm("mul.rn.f32x2 %0,%1,%2;" : "=l"(d) : "l"(a), "l"(b)); return d;
}
static __device__ __forceinline__ float ex2(float x) {
    float r; asm("ex2.approx.ftz.f32 %0,%1;" : "=f"(r) : "f"(x)); return r;
}

// --- one-time: scaled bilateral feats. u = f*sqrt(log2 e); h = |u|^2/2.
// Kbl = 2^(u.u' - h - h')
__global__ void prep_feats(const float* __restrict__ feat) {
    int i = blockIdx.x * blockDim.x + threadIdx.x;
    if (i >= NPTS) return;
    const float S = 1.2011224087864498f;  // sqrt(log2(e))
    float u[6]; float h = 0.0f;
#pragma unroll
    for (int d = 0; d < 6; d++) { u[d] = feat[d * NPTS + i] * S; h += u[d] * u[d]; }
    h *= 0.5f;
    float* r = g_prep + (size_t)i * 8;
    r[0] = u[0]; r[1] = u[1]; r[2] = u[2]; r[3] = u[3]; r[4] = u[4]; r[5] = u[5];
    r[6] = h; r[7] = 0.0f;
}

// --- one-time: spatial feature map phi_alpha(f) = e^{-|s|^2/2} s^a/sqrt(a!), s=f/8
__global__ void prep_phi(const float* __restrict__ feat) {
    int i = blockIdx.x * blockDim.x + threadIdx.x;
    if (i >= NPTS) return;
    float s0 = feat[0 * NPTS + i] * 0.125f;
    float s1 = feat[1 * NPTS + i] * 0.125f;
    float s2 = feat[2 * NPTS + i] * 0.125f;
    float ns = s0 * s0 + s1 * s1 + s2 * s2;
    float E = __expf(-0.5f * ns);
    float fact[7] = {1.f, 1.f, 2.f, 6.f, 24.f, 120.f, 720.f};
    int r = 0;
    float px = 1.0f;
    for (int ax = 0; ax <= 6; ax++) {
        float py = 1.0f;
        for (int ay = 0; ay <= 6 - ax; ay++) {
            float pz = 1.0f;
            for (int az = 0; az <= 6 - ax - ay; az++) {
                float rf = rsqrtf(fact[ax] * fact[ay] * fact[az]);
                g_phi[r * NPTS + i] = E * px * py * pz * rf;
                r++;
                pz *= s2;
            }
            py *= s1;
        }
        px *= s0;
    }
}

// --- one-time: bilateral kernel matrix in bf16.  g_K[j][i] (i fastest, bf16x2)
#define GTPB 128
#define GIPB 256
#define GJC  512
__global__ void __launch_bounds__(GTPB) genK_kernel() {
    __shared__ __align__(16) float sj[GJC * 8];  // 16KB
    int t = threadIdx.x, ib = blockIdx.x, js = blockIdx.y;
    int jbase = js * GJC;
    {
        const float4* src = (const float4*)(g_prep + (size_t)jbase * 8);
        float4* dst = (float4*)sj;
#pragma unroll
        for (int k = 0; k < (GJC * 8) / (4 * GTPB); k++)
            dst[t + k * GTPB] = src[t + k * GTPB];
    }
    __syncthreads();
    int i0 = ib * GIPB + 2 * t;
    const u64* r0 = (const u64*)(g_prep + (size_t)i0 * 8);
    const u64* r1 = (const u64*)(g_prep + (size_t)(i0 + 1) * 8);
    u64 a0 = r0[0], b0 = r0[1], c0 = r0[2];
    u64 a1 = r1[0], b1 = r1[1], c1 = r1[2];
    float h0, h1, du;
    unpack2(r0[3], h0, du);
    unpack2(r1[3], h1, du);
    u32* out = g_K + (size_t)jbase * (NPTS / 2) + (ib * (GIPB / 2) + t);
    const u64* sjj = (const u64*)sj;
#pragma unroll 2
    for (int j = 0; j < GJC; j++) {
        u64 ja = sjj[j * 4], jb = sjj[j * 4 + 1], jc = sjj[j * 4 + 2];
        float hj, d2;
        unpack2(sjj[j * 4 + 3], hj, d2);
        float x0, x1;
        {
            u64 d = fma2(a0, ja, fma2(b0, jb, mul2(c0, jc)));
            float lo, hi; unpack2(d, lo, hi);
            x0 = lo + hi - h0 - hj;
        }
        {
            u64 d = fma2(a1, ja, fma2(b1, jb, mul2(c1, jc)));
            float lo, hi; unpack2(d, lo, hi);
            x1 = lo + hi - h1 - hj;
        }
        float k0 = ex2(x0), k1 = ex2(x1);
        u32 kk; asm("cvt.rn.bf16x2.f32 %0,%1,%2;" : "=r"(kk) : "f"(k1), "f"(k0));
        out[(size_t)j * (NPTS / 2)] = kk;
    }
}

// --- per-iter: p = softmax(q); A = Ws p ; B = Wb p
__global__ void softmax_ab(const float* __restrict__ q,
                           const float* __restrict__ Ws,
                           const float* __restrict__ Wb) {
    __shared__ float sWs[C * C], sWb[C * C];
    int t = threadIdx.x;
    if (t < C * C) { sWs[t] = Ws[t]; sWb[t] = Wb[t]; }
    __syncthreads();
    int i = blockIdx.x * blockDim.x + t;
    if (i >= NPTS) return;
    float v[C];
    float m = -1e30f;
#pragma unroll
    for (int c = 0; c < C; c++) { v[c] = q[c * NPTS + i]; m = fmaxf(m, v[c]); }
    float s = 0.0f;
#pragma unroll
    for (int c = 0; c < C; c++) { v[c] = __expf(v[c] - m); s += v[c]; }
    float inv = 1.0f / s;
#pragma unroll
    for (int c = 0; c < C; c++) v[c] *= inv;
#pragma unroll
    for (int c = 0; c < C; c++) {
        float a = 0.0f, b = 0.0f;
#pragma unroll
        for (int cc = 0; cc < C; cc++) {
            a = fmaf(sWs[c * C + cc], v[cc], a);
            b = fmaf(sWb[c * C + cc], v[cc], b);
        }
        g_A[c * NPTS + i] = a;
        g_B[(size_t)i * 12 + c] = b;
    }
}

// --- per-iter: T[r][c] = sum_i A[c][i] * phi[r][i]
__global__ void T_kernel() {
    int r = blockIdx.x, t = threadIdx.x;
    float acc[C];
#pragma unroll
    for (int c = 0; c < C; c++) acc[c] = 0.0f;
    for (int i = t; i < NPTS; i += 256) {
        float ph = g_phi[r * NPTS + i];
#pragma unroll
        for (int c = 0; c < C; c++) acc[c] = fmaf(g_A[c * NPTS + i], ph, acc[c]);
    }
    __shared__ float s[C][256];
#pragma unroll
    for (int c = 0; c < C; c++) s[c][t] = acc[c];
    __syncthreads();
    for (int w = 128; w > 0; w >>= 1) {
        if (t < w)
#pragma unroll
            for (int c = 0; c < C; c++) s[c][t] += s[c][t + w];
        __syncthreads();
    }
    if (t < C) g_T[r * 12 + t] = s[t][0];
}

// --- per-iter hot loop: bilateral msg partials = B @ K  (K bf16, streamed)
#define FTPB 128
#define FIPT 4
#define FIPB 512   // 16 i-tiles
#define FJS  32
#define FJC  256
__global__ void __launch_bounds__(FTPB) filter_bl() {
    __shared__ __align__(16) float sB[FJC * 12];  // 12KB
    int t = threadIdx.x, ib = blockIdx.x, js = blockIdx.y;
    {
        const float4* src = (const float4*)(g_B + (size_t)js * FJC * 12);
        float4* dst = (float4*)sB;
#pragma unroll
        for (int k = 0; k < (FJC * 12) / (4 * FTPB); k++)
            dst[t + k * FTPB] = src[t + k * FTPB];
    }
    __syncthreads();
    int ibase = ib * FIPB + t * 4;
    const u64* Krow = ((const u64*)g_K) + (size_t)js * FJC * (NPTS / 4) + (ibase >> 2);
    u64 acc[4][5];
#pragma unroll
    for (int x = 0; x < 4; x++)
#pragma unroll
        for (int p = 0; p < 5; p++) acc[x][p] = 0;

#pragma unroll 4
    for (int j = 0; j < FJC; j++) {
        u64 kv = Krow[(size_t)j * (NPTS / 4)];
        u32 lo = (u32)kv, hi = (u32)(kv >> 32);
        float k0 = __uint_as_float(lo << 16);
        float k1 = __uint_as_float(lo & 0xffff0000u);
        float k2 = __uint_as_float(hi << 16);
        float k3 = __uint_as_float(hi & 0xffff0000u);
        u64 kd[4];
        kd[0] = pack2(k0, k0); kd[1] = pack2(k1, k1);
        kd[2] = pack2(k2, k2); kd[3] = pack2(k3, k3);
        const u64* bj = (const u64*)(sB + j * 12);
        u64 b0 = bj[0], b1 = bj[1], b2 = bj[2], b3 = bj[3], b4 = bj[4];
#pragma unroll
        for (int x = 0; x < 4; x++) {
            acc[x][0] = fma2(kd[x], b0, acc[x][0]);
            acc[x][1] = fma2(kd[x], b1, acc[x][1]);
            acc[x][2] = fma2(kd[x], b2, acc[x][2]);
            acc[x][3] = fma2(kd[x], b3, acc[x][3]);
            acc[x][4] = fma2(kd[x], b4, acc[x][4]);
        }
    }

    float* P = g_partial + (size_t)js * C * NPTS;
#pragma unroll
    for (int x = 0; x < 4; x++)
#pragma unroll
        for (int p = 0; p < 5; p++) {
            float lo, hi;
            unpack2(acc[x][p], lo, hi);
            P[(2 * p) * NPTS + ibase + x] = lo;
            P[(2 * p + 1) * NPTS + ibase + x] = hi;
        }
}

// --- per-iter: combine partials + spatial low-rank + compatibility
__global__ void reduce_kernel(const float* __restrict__ unaries,
                              const float* __restrict__ compat,
                              float* __restrict__ q) {
    __shared__ float sT[NPHI * 12];
    __shared__ float sC[C * C];
    int t = threadIdx.x;
    for (int k = t; k < NPHI * 12; k += 256) sT[k] = g_T[k];
    if (t < C * C) sC[t] = compat[t];
    __syncthreads();
    int i = blockIdx.x * 256 + t;
    float m[C];
#pragma unroll
    for (int c = 0; c < C; c++) {
        float s = 0.0f;
#pragma unroll
        for (int js = 0; js < FJS; js++)
            s += g_partial[((size_t)js * C + c) * NPTS + i];
        m[c] = s;
    }
    for (int r = 0; r < NPHI; r++) {
        float ph = g_phi[r * NPTS + i];
#pragma unroll
        for (int c = 0; c < C; c++) m[c] = fmaf(sT[r * 12 + c], ph, m[c]);
    }
#pragma unroll
    for (int c = 0; c < C; c++) {
        float acc = unaries[c * NPTS + i];
#pragma unroll
        for (int cc = 0; cc < C; cc++)
            acc = fmaf(-sC[c * C + cc], m[cc], acc);
        q[c * NPTS + i] = acc;
    }
}

extern "C" void kernel_launch(void* const* d_in, const int* in_sizes, int n_in,
                              void* d_out, int out_size) {
    const float* unaries = (const float*)d_in[0];
    const float* feat    = (const float*)d_in[1];
    const float* Ws      = (const float*)d_in[2];
    const float* Wb      = (const float*)d_in[3];
    const float* compat  = (const float*)d_in[4];
    float* q = (float*)d_out;

    prep_feats<<<NPTS / 256, 256>>>(feat);
    prep_phi<<<NPTS / 256, 256>>>(feat);
    genK_kernel<<<dim3(NPTS / GIPB, NPTS / GJC), GTPB>>>();
    for (int it = 0; it < 5; it++) {
        softmax_ab<<<NPTS / 256, 256>>>(it == 0 ? unaries : q, Ws, Wb);
        T_kernel<<<NPHI, 256>>>();
        filter_bl<<<dim3(NPTS / FIPB, FJS), FTPB>>>();
        reduce_kernel<<<NPTS / 256, 256>>>(unaries, compat, q);
    }
}

// round 9
// speedup vs baseline: 1.8922x; 1.8852x over previous
#include <cuda_runtime.h>
#include <math.h>
#include <stdint.h>

#define NPTS 8192
#define C    10
#define NPHI 84
#define NT   64            // 128-row i tiles
#define NJC  256           // 32-col j chunks
#define KCH_BYTES 4096     // 128x32 int8 K chunk
#define BCH_BYTES 512      // 16x32  int8 B chunk
#define JSPLIT 8
#define NCH (NJC / JSPLIT) // 32 chunks per CTA
#define NSTAGE 4
#define BUF_STRIDE 4608    // 4KB K + 512B B

typedef unsigned long long u64;
typedef unsigned int u32;
typedef unsigned char u8;

// ---- static scratch ----
__device__ __align__(16) float g_prep[NPTS * 8];
__device__ __align__(16) float g_phi[NPHI * NPTS];
__device__ __align__(128) u8  g_K[(size_t)NT * NJC * KCH_BYTES];  // s8 round(K*127), [ti][jc][i128][j32]
__device__ __align__(128) u8  g_B[NJC * BCH_BYTES];               // s8 round(b*127), [jc][c16][j32]
__device__ __align__(16) float g_A[C * NPTS];
__device__ __align__(16) float g_T[NPHI * 12];
__device__ __align__(16) float g_partial[JSPLIT * C * NPTS];

// ---- helpers ----
static __device__ __forceinline__ void unpack2(u64 v, float& lo, float& hi) {
    asm("mov.b64 {%0,%1},%2;" : "=f"(lo), "=f"(hi) : "l"(v));
}
static __device__ __forceinline__ u64 fma2(u64 a, u64 b, u64 c) {
    u64 d; asm("fma.rn.f32x2 %0,%1,%2,%3;" : "=l"(d) : "l"(a), "l"(b), "l"(c)); return d;
}
static __device__ __forceinline__ u64 mul2(u64 a, u64 b) {
    u64 d; asm("mul.rn.f32x2 %0,%1,%2;" : "=l"(d) : "l"(a), "l"(b)); return d;
}
static __device__ __forceinline__ float ex2(float x) {
    float r; asm("ex2.approx.ftz.f32 %0,%1;" : "=f"(r) : "f"(x)); return r;
}
static __device__ __forceinline__ u32 smem_u32(const void* p) {
    u32 a; asm("{ .reg .u64 t; cvta.to.shared.u64 t, %1; cvt.u32.u64 %0, t; }" : "=r"(a) : "l"(p));
    return a;
}
static __device__ __forceinline__ void cp16(u32 s, const void* g) {
    asm volatile("cp.async.cg.shared.global [%0], [%1], 16;" :: "r"(s), "l"(g) : "memory");
}
#define CP_COMMIT() asm volatile("cp.async.commit_group;" ::: "memory")
#define CP_WAIT(n)  asm volatile("cp.async.wait_group %0;" :: "n"(n) : "memory")

static __device__ __forceinline__ void ldsm_x4(u32& r0, u32& r1, u32& r2, u32& r3, u32 a) {
    asm volatile("ldmatrix.sync.aligned.m8n8.x4.shared.b16 {%0,%1,%2,%3}, [%4];"
        : "=r"(r0), "=r"(r1), "=r"(r2), "=r"(r3) : "r"(a));
}
static __device__ __forceinline__ void ldsm_x2(u32& r0, u32& r1, u32 a) {
    asm volatile("ldmatrix.sync.aligned.m8n8.x2.shared.b16 {%0,%1}, [%2];"
        : "=r"(r0), "=r"(r1) : "r"(a));
}
static __device__ __forceinline__ void mma_s8(int* d, const u32* a, const u32* b) {
    asm volatile("mma.sync.aligned.m16n8k32.row.col.s32.s8.s8.s32 "
        "{%0,%1,%2,%3}, {%4,%5,%6,%7}, {%8,%9}, {%0,%1,%2,%3};"
        : "+r"(d[0]), "+r"(d[1]), "+r"(d[2]), "+r"(d[3])
        : "r"(a[0]), "r"(a[1]), "r"(a[2]), "r"(a[3]), "r"(b[0]), "r"(b[1]));
}

// ============ one-time kernels ============
__global__ void prep_feats(const float* __restrict__ feat) {
    int i = blockIdx.x * blockDim.x + threadIdx.x;
    if (i >= NPTS) return;
    const float S = 1.2011224087864498f;  // sqrt(log2 e):  K = 2^(u.u' - h - h')
    float u[6]; float h = 0.0f;
#pragma unroll
    for (int d = 0; d < 6; d++) { u[d] = feat[d * NPTS + i] * S; h += u[d] * u[d]; }
    h *= 0.5f;
    float* r = g_prep + (size_t)i * 8;
#pragma unroll
    for (int d = 0; d < 6; d++) r[d] = u[d];
    r[6] = h; r[7] = 0.0f;
}

__global__ void prep_phi(const float* __restrict__ feat) {
    int i = blockIdx.x * blockDim.x + threadIdx.x;
    if (i >= NPTS) return;
    float s0 = feat[0 * NPTS + i] * 0.125f;
    float s1 = feat[1 * NPTS + i] * 0.125f;
    float s2 = feat[2 * NPTS + i] * 0.125f;
    float E = __expf(-0.5f * (s0 * s0 + s1 * s1 + s2 * s2));
    float fact[7] = {1.f, 1.f, 2.f, 6.f, 24.f, 120.f, 720.f};
    int r = 0;
    float px = 1.0f;
    for (int ax = 0; ax <= 6; ax++) {
        float py = 1.0f;
        for (int ay = 0; ay <= 6 - ax; ay++) {
            float pz = 1.0f;
            for (int az = 0; az <= 6 - ax - ay; az++) {
                g_phi[r * NPTS + i] = E * px * py * pz * rsqrtf(fact[ax] * fact[ay] * fact[az]);
                r++; pz *= s2;
            }
            py *= s1;
        }
        px *= s0;
    }
}

__global__ void zero_gB() {
    int k = blockIdx.x * 256 + threadIdx.x;
    if (k < NJC * BCH_BYTES / 4) ((u32*)g_B)[k] = 0;
}

// K chunk generator: s8 round(K*127), layout [ti][jc][i 128][j 32]
__global__ void __launch_bounds__(128) genK() {
    __shared__ __align__(16) float sj[128 * 8];
    int tid = threadIdx.x, ti = blockIdx.x, tj = blockIdx.y;
    {
        const float4* src = (const float4*)(g_prep + (size_t)tj * 128 * 8);
        float4* dst = (float4*)sj;
        dst[tid] = src[tid];
        dst[tid + 128] = src[tid + 128];
    }
    __syncthreads();
    int i = ti * 128 + tid;
    const u64* ir = (const u64*)(g_prep + (size_t)i * 8);
    u64 a0 = ir[0], a1 = ir[1], a2 = ir[2];
    float hi_, du; unpack2(ir[3], hi_, du);
    float ci = 6.9886846867721655f - hi_;  // log2(127) - h_i : folds *127 into exponent
    const u64* sj64 = (const u64*)sj;
    u32* outw = (u32*)g_K;
#pragma unroll 2
    for (int j0 = 0; j0 < 128; j0 += 4) {
        u32 word = 0;
#pragma unroll
        for (int e = 0; e < 4; e++) {
            int j = j0 + e;
            u64 s0 = sj64[j * 4], s1 = sj64[j * 4 + 1], s2 = sj64[j * 4 + 2];
            float hj, d2; unpack2(sj64[j * 4 + 3], hj, d2);
            u64 d = fma2(a0, s0, fma2(a1, s1, mul2(a2, s2)));
            float lo, hh; unpack2(d, lo, hh);
            int v = __float2int_rn(ex2(lo + hh + (ci - hj)));  // [0,127]
            word |= ((u32)(v & 0xFF)) << (8 * e);
        }
        size_t jc = (size_t)ti * NJC + tj * 4 + (j0 >> 5);
        outw[(jc * 128 + tid) * 8 + ((j0 & 31) >> 2)] = word;
    }
}

// ============ per-iteration kernels ============
__global__ void softmax_ab(const float* __restrict__ q,
                           const float* __restrict__ Ws,
                           const float* __restrict__ Wb) {
    __shared__ float sWs[C * C], sWb[C * C];
    int t = threadIdx.x;
    if (t < C * C) { sWs[t] = Ws[t]; sWb[t] = Wb[t]; }
    __syncthreads();
    int i = blockIdx.x * blockDim.x + t;
    if (i >= NPTS) return;
    float v[C];
    float m = -1e30f;
#pragma unroll
    for (int c = 0; c < C; c++) { v[c] = q[c * NPTS + i]; m = fmaxf(m, v[c]); }
    float s = 0.0f;
#pragma unroll
    for (int c = 0; c < C; c++) { v[c] = __expf(v[c] - m); s += v[c]; }
    float inv = 1.0f / s;
#pragma unroll
    for (int c = 0; c < C; c++) v[c] *= inv;
    u8* bdst = g_B + (size_t)(i >> 5) * BCH_BYTES + (i & 31);
#pragma unroll
    for (int c = 0; c < C; c++) {
        float a = 0.0f, b = 0.0f;
#pragma unroll
        for (int cc = 0; cc < C; cc++) {
            a = fmaf(sWs[c * C + cc], v[cc], a);
            b = fmaf(sWb[c * C + cc], v[cc], b);
        }
        g_A[c * NPTS + i] = a;
        int iv = __float2int_rn(b * 127.0f);
        iv = iv > 127 ? 127 : (iv < -127 ? -127 : iv);
        bdst[c * 32] = (u8)(iv & 0xFF);
    }
}

__global__ void T_kernel() {
    int r = blockIdx.x, t = threadIdx.x;
    float acc[C];
#pragma unroll
    for (int c = 0; c < C; c++) acc[c] = 0.0f;
    for (int i = t; i < NPTS; i += 256) {
        float ph = g_phi[r * NPTS + i];
#pragma unroll
        for (int c = 0; c < C; c++) acc[c] = fmaf(g_A[c * NPTS + i], ph, acc[c]);
    }
    __shared__ float s[C][256];
#pragma unroll
    for (int c = 0; c < C; c++) s[c][t] = acc[c];
    __syncthreads();
    for (int w = 128; w > 0; w >>= 1) {
        if (t < w)
#pragma unroll
            for (int c = 0; c < C; c++) s[c][t] += s[c][t + w];
        __syncthreads();
    }
    if (t < C) g_T[r * 12 + t] = s[t][0];
}

// ---- bilateral GEMM via mma.sync s8, cp.async.cg quad-buffered ----
__global__ void __launch_bounds__(128) gemm_bl() {
    __shared__ __align__(128) u8 pool[NSTAGE * BUF_STRIDE];
    u32 base = smem_u32(pool);
    int tid = threadIdx.x, w = tid >> 5, l = tid & 31;
    int ti = blockIdx.x, js = blockIdx.y;

    // ldmatrix source addresses (per-lane rows)
    u32 aoff[2], boff[2];
#pragma unroll
    for (int t = 0; t < 2; t++) {
        int m = l >> 3, r = l & 7;
        aoff[t] = (u32)((w * 32 + t * 16 + (m & 1) * 8 + r) * 32 + (m >> 1) * 16);
    }
#pragma unroll
    for (int n = 0; n < 2; n++) {
        int ll = l & 15;
        boff[n] = (u32)(4096 + (n * 8 + (ll & 7)) * 32 + ((ll >> 3) & 1) * 16);
    }

    int acc[2][2][4];
#pragma unroll
    for (int t = 0; t < 2; t++)
#pragma unroll
        for (int n = 0; n < 2; n++)
#pragma unroll
            for (int k = 0; k < 4; k++) acc[t][n][k] = 0;

    int jc0 = js * NCH;
    const u8* ksrc = g_K + ((size_t)ti * NJC + jc0) * KCH_BYTES;
    const u8* bsrc = g_B + (size_t)jc0 * BCH_BYTES;

    // prologue: fill NSTAGE stages
#pragma unroll
    for (int ch = 0; ch < NSTAGE; ch++) {
        u32 bufb = base + (ch % NSTAGE) * BUF_STRIDE;
        const u8* kp = ksrc + (size_t)ch * KCH_BYTES;
        cp16(bufb + tid * 16, kp + tid * 16);
        cp16(bufb + (tid + 128) * 16, kp + (tid + 128) * 16);
        if (tid < 32) cp16(bufb + 4096 + tid * 16, bsrc + (size_t)ch * BCH_BYTES + tid * 16);
        CP_COMMIT();
    }

    for (int ch = 0; ch < NCH; ch++) {
        CP_WAIT(NSTAGE - 1);
        __syncthreads();
        u32 bufb = base + (ch % NSTAGE) * BUF_STRIDE;
        u32 afrag[2][4]; u32 bfrag[2][2];
#pragma unroll
        for (int t = 0; t < 2; t++)
            ldsm_x4(afrag[t][0], afrag[t][1], afrag[t][2], afrag[t][3], bufb + aoff[t]);
#pragma unroll
        for (int n = 0; n < 2; n++)
            ldsm_x2(bfrag[n][0], bfrag[n][1], bufb + boff[n]);
#pragma unroll
        for (int t = 0; t < 2; t++)
#pragma unroll
            for (int n = 0; n < 2; n++)
                mma_s8(acc[t][n], afrag[t], bfrag[n]);
        __syncthreads();
        // refill this stage with chunk ch+NSTAGE
        int nch = ch + NSTAGE;
        if (nch < NCH) {
            const u8* kp = ksrc + (size_t)nch * KCH_BYTES;
            cp16(bufb + tid * 16, kp + tid * 16);
            cp16(bufb + (tid + 128) * 16, kp + (tid + 128) * 16);
            if (tid < 32) cp16(bufb + 4096 + tid * 16, bsrc + (size_t)nch * BCH_BYTES + tid * 16);
        }
        CP_COMMIT();
    }
    CP_WAIT(0);

    const float sc = 1.0f / 16129.0f;  // 1/(127*127)
    float* P = g_partial + (size_t)js * C * NPTS;
#pragma unroll
    for (int t = 0; t < 2; t++) {
        int row0 = ti * 128 + w * 32 + t * 16 + (l >> 2);
#pragma unroll
        for (int n = 0; n < 2; n++) {
            int c0 = n * 8 + 2 * (l & 3);
#pragma unroll
            for (int h = 0; h < 2; h++) {
                int row = row0 + h * 8;
                if (c0 < C)     P[c0 * NPTS + row]       = (float)acc[t][n][h * 2 + 0] * sc;
                if (c0 + 1 < C) P[(c0 + 1) * NPTS + row] = (float)acc[t][n][h * 2 + 1] * sc;
            }
        }
    }
}

__global__ void reduce_kernel(const float* __restrict__ unaries,
                              const float* __restrict__ compat,
                              float* __restrict__ q) {
    __shared__ float sT[NPHI * 12];
    __shared__ float sC[C * C];
    int t = threadIdx.x;
    for (int k = t; k < NPHI * 12; k += 256) sT[k] = g_T[k];
    if (t < C * C) sC[t] = compat[t];
    __syncthreads();
    int i = blockIdx.x * 256 + t;
    float m[C];
#pragma unroll
    for (int c = 0; c < C; c++) {
        float s = 0.0f;
#pragma unroll
        for (int js = 0; js < JSPLIT; js++)
            s += g_partial[((size_t)js * C + c) * NPTS + i];
        m[c] = s;
    }
    for (int r = 0; r < NPHI; r++) {
        float ph = g_phi[r * NPTS + i];
#pragma unroll
        for (int c = 0; c < C; c++) m[c] = fmaf(sT[r * 12 + c], ph, m[c]);
    }
#pragma unroll
    for (int c = 0; c < C; c++) {
        float acc = unaries[c * NPTS + i];
#pragma unroll
        for (int cc = 0; cc < C; cc++)
            acc = fmaf(-sC[c * C + cc], m[cc], acc);
        q[c * NPTS + i] = acc;
    }
}

extern "C" void kernel_launch(void* const* d_in, const int* in_sizes, int n_in,
                              void* d_out, int out_size) {
    const float* unaries = (const float*)d_in[0];
    const float* feat    = (const float*)d_in[1];
    const float* Ws      = (const float*)d_in[2];
    const float* Wb      = (const float*)d_in[3];
    const float* compat  = (const float*)d_in[4];
    float* q = (float*)d_out;

    prep_feats<<<NPTS / 256, 256>>>(feat);
    prep_phi<<<NPTS / 256, 256>>>(feat);
    zero_gB<<<(NJC * BCH_BYTES / 4 + 255) / 256, 256>>>();
    genK<<<dim3(NT, NT), 128>>>();
    for (int it = 0; it < 5; it++) {
        softmax_ab<<<NPTS / 128, 128>>>(it == 0 ? unaries : q, Ws, Wb);
        T_kernel<<<NPHI, 256>>>();
        gemm_bl<<<dim3(NT, JSPLIT), 128>>>();
        reduce_kernel<<<NPTS / 256, 256>>>(unaries, compat, q);
    }
}

// round 15
// speedup vs baseline: 1.9045x; 1.0065x over previous
#include <cuda_runtime.h>
#include <math.h>
#include <stdint.h>

#define NPTS 8192
#define C    10
#define NPHI 84
#define NT   64            // 128-row i tiles
#define NJC  256           // 32-col j chunks
#define KCH_BYTES 4096     // 128x32 int8 K chunk
#define BCH_BYTES 512      // 16x32  int8 B chunk
#define JSPLIT 16
#define NCH (NJC / JSPLIT) // 16 chunks per CTA
#define NSTAGE 4
#define BUF_STRIDE 4608    // 4KB K + 512B B

typedef unsigned long long u64;
typedef unsigned int u32;
typedef unsigned char u8;

// ---- static scratch ----
__device__ __align__(16) float g_prep[NPTS * 8];
__device__ __align__(16) float g_phi[NPHI * NPTS];
__device__ __align__(128) u8  g_K[(size_t)NT * NJC * KCH_BYTES];  // s8 round(K*127), [ti][jc][i128][j32]
__device__ __align__(128) u8  g_B[NJC * BCH_BYTES];               // s8 round(b*127), [jc][c16][j32]
__device__ __align__(16) float g_A[C * NPTS];
__device__ __align__(16) float g_T[NPHI * 12];
__device__ __align__(16) float g_partial[JSPLIT * C * NPTS];

// ---- helpers ----
static __device__ __forceinline__ void unpack2(u64 v, float& lo, float& hi) {
    asm("mov.b64 {%0,%1},%2;" : "=f"(lo), "=f"(hi) : "l"(v));
}
static __device__ __forceinline__ u64 fma2(u64 a, u64 b, u64 c) {
    u64 d; asm("fma.rn.f32x2 %0,%1,%2,%3;" : "=l"(d) : "l"(a), "l"(b), "l"(c)); return d;
}
static __device__ __forceinline__ u64 mul2(u64 a, u64 b) {
    u64 d; asm("mul.rn.f32x2 %0,%1,%2;" : "=l"(d) : "l"(a), "l"(b)); return d;
}
static __device__ __forceinline__ float ex2(float x) {
    float r; asm("ex2.approx.ftz.f32 %0,%1;" : "=f"(r) : "f"(x)); return r;
}
static __device__ __forceinline__ u32 smem_u32(const void* p) {
    u32 a; asm("{ .reg .u64 t; cvta.to.shared.u64 t, %1; cvt.u32.u64 %0, t; }" : "=r"(a) : "l"(p));
    return a;
}
static __device__ __forceinline__ void cp16(u32 s, const void* g) {
    asm volatile("cp.async.cg.shared.global [%0], [%1], 16;" :: "r"(s), "l"(g) : "memory");
}
#define CP_COMMIT() asm volatile("cp.async.commit_group;" ::: "memory")
#define CP_WAIT(n)  asm volatile("cp.async.wait_group %0;" :: "n"(n) : "memory")

static __device__ __forceinline__ void ldsm_x4(u32& r0, u32& r1, u32& r2, u32& r3, u32 a) {
    asm volatile("ldmatrix.sync.aligned.m8n8.x4.shared.b16 {%0,%1,%2,%3}, [%4];"
        : "=r"(r0), "=r"(r1), "=r"(r2), "=r"(r3) : "r"(a));
}
static __device__ __forceinline__ void ldsm_x2(u32& r0, u32& r1, u32 a) {
    asm volatile("ldmatrix.sync.aligned.m8n8.x2.shared.b16 {%0,%1}, [%2];"
        : "=r"(r0), "=r"(r1) : "r"(a));
}
static __device__ __forceinline__ void mma_s8(int* d, const u32* a, const u32* b) {
    asm volatile("mma.sync.aligned.m16n8k32.row.col.s32.s8.s8.s32 "
        "{%0,%1,%2,%3}, {%4,%5,%6,%7}, {%8,%9}, {%0,%1,%2,%3};"
        : "+r"(d[0]), "+r"(d[1]), "+r"(d[2]), "+r"(d[3])
        : "r"(a[0]), "r"(a[1]), "r"(a[2]), "r"(a[3]), "r"(b[0]), "r"(b[1]));
}

// ============ one-time kernels ============
__global__ void prep_feats(const float* __restrict__ feat) {
    int i = blockIdx.x * blockDim.x + threadIdx.x;
    if (i >= NPTS) return;
    const float S = 1.2011224087864498f;  // sqrt(log2 e):  K = 2^(u.u' - h - h')
    float u[6]; float h = 0.0f;
#pragma unroll
    for (int d = 0; d < 6; d++) { u[d] = feat[d * NPTS + i] * S; h += u[d] * u[d]; }
    h *= 0.5f;
    float* r = g_prep + (size_t)i * 8;
#pragma unroll
    for (int d = 0; d < 6; d++) r[d] = u[d];
    r[6] = h; r[7] = 0.0f;
}

__global__ void prep_phi(const float* __restrict__ feat) {
    int i = blockIdx.x * blockDim.x + threadIdx.x;
    if (i >= NPTS) return;
    float s0 = feat[0 * NPTS + i] * 0.125f;
    float s1 = feat[1 * NPTS + i] * 0.125f;
    float s2 = feat[2 * NPTS + i] * 0.125f;
    float E = __expf(-0.5f * (s0 * s0 + s1 * s1 + s2 * s2));
    float fact[7] = {1.f, 1.f, 2.f, 6.f, 24.f, 120.f, 720.f};
    int r = 0;
    float px = 1.0f;
    for (int ax = 0; ax <= 6; ax++) {
        float py = 1.0f;
        for (int ay = 0; ay <= 6 - ax; ay++) {
            float pz = 1.0f;
            for (int az = 0; az <= 6 - ax - ay; az++) {
                g_phi[r * NPTS + i] = E * px * py * pz * rsqrtf(fact[ax] * fact[ay] * fact[az]);
                r++; pz *= s2;
            }
            py *= s1;
        }
        px *= s0;
    }
}

__global__ void zero_gB() {
    int k = blockIdx.x * 256 + threadIdx.x;
    if (k < NJC * BCH_BYTES / 4) ((u32*)g_B)[k] = 0;
}

// K chunk generator: s8 round(K*127), layout [ti][jc][i 128][j 32]
// Output staged in smem, then written with coalesced float4 stores. (R9-proven)
__global__ void __launch_bounds__(128) genK() {
    __shared__ __align__(16) float sj[128 * 8];   // 4KB j-features
    __shared__ __align__(16) u32 stile[4096];     // 16KB staged output tile
    int tid = threadIdx.x, ti = blockIdx.x, tj = blockIdx.y;
    {
        const float4* src = (const float4*)(g_prep + (size_t)tj * 128 * 8);
        float4* dst = (float4*)sj;
        dst[tid] = src[tid];
        dst[tid + 128] = src[tid + 128];
    }
    __syncthreads();
    int i = ti * 128 + tid;
    const u64* ir = (const u64*)(g_prep + (size_t)i * 8);
    u64 a0 = ir[0], a1 = ir[1], a2 = ir[2];
    float hi_, du; unpack2(ir[3], hi_, du);
    float ci = 6.9886846867721655f - hi_;  // log2(127) - h_i : folds *127 into exponent
    const u64* sj64 = (const u64*)sj;
#pragma unroll 2
    for (int j0 = 0; j0 < 128; j0 += 4) {
        u32 word = 0;
#pragma unroll
        for (int e = 0; e < 4; e++) {
            int j = j0 + e;
            u64 s0 = sj64[j * 4], s1 = sj64[j * 4 + 1], s2 = sj64[j * 4 + 2];
            float hj, d2; unpack2(sj64[j * 4 + 3], hj, d2);
            u64 d = fma2(a0, s0, fma2(a1, s1, mul2(a2, s2)));
            float lo, hh; unpack2(d, lo, hh);
            int v = __float2int_rn(ex2(lo + hh + (ci - hj)));  // [0,127]
            word |= ((u32)(v & 0xFF)) << (8 * e);
        }
        stile[((j0 >> 5) << 10) + (tid << 3) + ((j0 & 31) >> 2)] = word;
    }
    __syncthreads();
    float4* g4 = (float4*)(g_K + ((size_t)ti * NJC + (size_t)tj * 4) * KCH_BYTES);
    const float4* s4 = (const float4*)stile;
#pragma unroll
    for (int k = 0; k < 8; k++)
        g4[tid + k * 128] = s4[tid + k * 128];
}

// ---- shared softmax->A,B body ----
static __device__ __forceinline__ void softmax_store(const float* v_in, int i,
                                                     const float* sWs, const float* sWb) {
    float v[C];
    float m = -1e30f;
#pragma unroll
    for (int c = 0; c < C; c++) { v[c] = v_in[c]; m = fmaxf(m, v[c]); }
    float s = 0.0f;
#pragma unroll
    for (int c = 0; c < C; c++) { v[c] = __expf(v[c] - m); s += v[c]; }
    float inv = 1.0f / s;
#pragma unroll
    for (int c = 0; c < C; c++) v[c] *= inv;
    u8* bdst = g_B + (size_t)(i >> 5) * BCH_BYTES + (i & 31);
#pragma unroll
    for (int c = 0; c < C; c++) {
        float a = 0.0f, b = 0.0f;
#pragma unroll
        for (int cc = 0; cc < C; cc++) {
            a = fmaf(sWs[c * C + cc], v[cc], a);
            b = fmaf(sWb[c * C + cc], v[cc], b);
        }
        g_A[c * NPTS + i] = a;
        int iv = __float2int_rn(b * 127.0f);
        iv = iv > 127 ? 127 : (iv < -127 ? -127 : iv);
        bdst[c * 32] = (u8)(iv & 0xFF);
    }
}

// iteration 0: softmax of unaries
__global__ void softmax0(const float* __restrict__ unaries,
                         const float* __restrict__ Ws,
                         const float* __restrict__ Wb) {
    __shared__ float sWs[C * C], sWb[C * C];
    int t = threadIdx.x;
    if (t < C * C) { sWs[t] = Ws[t]; sWb[t] = Wb[t]; }
    __syncthreads();
    int i = blockIdx.x * blockDim.x + t;
    if (i >= NPTS) return;
    float v[C];
#pragma unroll
    for (int c = 0; c < C; c++) v[c] = unaries[c * NPTS + i];
    softmax_store(v, i, sWs, sWb);
}

__global__ void T_kernel() {
    int r = blockIdx.x, t = threadIdx.x;
    float acc[C];
#pragma unroll
    for (int c = 0; c < C; c++) acc[c] = 0.0f;
    for (int i = t; i < NPTS; i += 256) {
        float ph = g_phi[r * NPTS + i];
#pragma unroll
        for (int c = 0; c < C; c++) acc[c] = fmaf(g_A[c * NPTS + i], ph, acc[c]);
    }
    __shared__ float s[C][256];
#pragma unroll
    for (int c = 0; c < C; c++) s[c][t] = acc[c];
    __syncthreads();
    for (int w = 128; w > 0; w >>= 1) {
        if (t < w)
#pragma unroll
            for (int c = 0; c < C; c++) s[c][t] += s[c][t + w];
        __syncthreads();
    }
    if (t < C) g_T[r * 12 + t] = s[t][0];
}

// ---- bilateral GEMM via mma.sync s8, cp.async.cg quad-buffered (R9-proven body) ----
__global__ void __launch_bounds__(128) gemm_bl() {
    __shared__ __align__(128) u8 pool[NSTAGE * BUF_STRIDE];
    u32 base = smem_u32(pool);
    int tid = threadIdx.x, w = tid >> 5, l = tid & 31;
    int ti = blockIdx.x, js = blockIdx.y;

    u32 aoff[2], boff[2];
#pragma unroll
    for (int t = 0; t < 2; t++) {
        int m = l >> 3, r = l & 7;
        aoff[t] = (u32)((w * 32 + t * 16 + (m & 1) * 8 + r) * 32 + (m >> 1) * 16);
    }
#pragma unroll
    for (int n = 0; n < 2; n++) {
        int ll = l & 15;
        boff[n] = (u32)(4096 + (n * 8 + (ll & 7)) * 32 + ((ll >> 3) & 1) * 16);
    }

    int acc[2][2][4];
#pragma unroll
    for (int t = 0; t < 2; t++)
#pragma unroll
        for (int n = 0; n < 2; n++)
#pragma unroll
            for (int k = 0; k < 4; k++) acc[t][n][k] = 0;

    int jc0 = js * NCH;
    const u8* ksrc = g_K + ((size_t)ti * NJC + jc0) * KCH_BYTES;
    const u8* bsrc = g_B + (size_t)jc0 * BCH_BYTES;

    // prologue: fill NSTAGE stages
#pragma unroll
    for (int ch = 0; ch < NSTAGE; ch++) {
        u32 bufb = base + ch * BUF_STRIDE;
        const u8* kp = ksrc + (size_t)ch * KCH_BYTES;
        cp16(bufb + tid * 16, kp + tid * 16);
        cp16(bufb + (tid + 128) * 16, kp + (tid + 128) * 16);
        if (tid < 32) cp16(bufb + 4096 + tid * 16, bsrc + (size_t)ch * BCH_BYTES + tid * 16);
        CP_COMMIT();
    }

#pragma unroll 4
    for (int ch = 0; ch < NCH; ch++) {
        CP_WAIT(NSTAGE - 1);
        __syncthreads();
        u32 bufb = base + (ch % NSTAGE) * BUF_STRIDE;
        u32 afrag[2][4]; u32 bfrag[2][2];
#pragma unroll
        for (int t = 0; t < 2; t++)
            ldsm_x4(afrag[t][0], afrag[t][1], afrag[t][2], afrag[t][3], bufb + aoff[t]);
#pragma unroll
        for (int n = 0; n < 2; n++)
            ldsm_x2(bfrag[n][0], bfrag[n][1], bufb + boff[n]);
#pragma unroll
        for (int t = 0; t < 2; t++)
#pragma unroll
            for (int n = 0; n < 2; n++)
                mma_s8(acc[t][n], afrag[t], bfrag[n]);
        __syncthreads();
        int nch = ch + NSTAGE;
        if (nch < NCH) {
            const u8* kp = ksrc + (size_t)nch * KCH_BYTES;
            cp16(bufb + tid * 16, kp + tid * 16);
            cp16(bufb + (tid + 128) * 16, kp + (tid + 128) * 16);
            if (tid < 32) cp16(bufb + 4096 + tid * 16, bsrc + (size_t)nch * BCH_BYTES + tid * 16);
        }
        CP_COMMIT();
    }
    CP_WAIT(0);

    const float sc = 1.0f / 16129.0f;  // 1/(127*127)
    float* P = g_partial + (size_t)js * C * NPTS;
#pragma unroll
    for (int t = 0; t < 2; t++) {
        int row0 = ti * 128 + w * 32 + t * 16 + (l >> 2);
#pragma unroll
        for (int n = 0; n < 2; n++) {
            int c0 = n * 8 + 2 * (l & 3);
#pragma unroll
            for (int h = 0; h < 2; h++) {
                int row = row0 + h * 8;
                if (c0 < C)     P[c0 * NPTS + row]       = (float)acc[t][n][h * 2 + 0] * sc;
                if (c0 + 1 < C) P[(c0 + 1) * NPTS + row] = (float)acc[t][n][h * 2 + 1] * sc;
            }
        }
    }
}

// ---- fused message-combine + q + softmax + A/B (iterations 1..4) ----
__global__ void update(const float* __restrict__ unaries,
                       const float* __restrict__ compat,
                       const float* __restrict__ Ws,
                       const float* __restrict__ Wb) {
    __shared__ float sT[NPHI * 12];
    __shared__ float sC[C * C], sWs[C * C], sWb[C * C];
    int t = threadIdx.x;
    for (int k = t; k < NPHI * 12; k += 256) sT[k] = g_T[k];
    if (t < C * C) { sC[t] = compat[t]; sWs[t] = Ws[t]; sWb[t] = Wb[t]; }
    __syncthreads();
    int i = blockIdx.x * 256 + t;
    float m[C];
#pragma unroll
    for (int c = 0; c < C; c++) {
        float s = 0.0f;
#pragma unroll
        for (int js = 0; js < JSPLIT; js++)
            s += g_partial[((size_t)js * C + c) * NPTS + i];
        m[c] = s;
    }
    for (int r = 0; r < NPHI; r++) {
        float ph = g_phi[r * NPTS + i];
#pragma unroll
        for (int c = 0; c < C; c++) m[c] = fmaf(sT[r * 12 + c], ph, m[c]);
    }
    float qv[C];
#pragma unroll
    for (int c = 0; c < C; c++) {
        float acc = unaries[c * NPTS + i];
#pragma unroll
        for (int cc = 0; cc < C; cc++)
            acc = fmaf(-sC[c * C + cc], m[cc], acc);
        qv[c] = acc;
    }
    softmax_store(qv, i, sWs, sWb);
}

// ---- final combine -> q written to d_out ----
__global__ void reduce_final(const float* __restrict__ unaries,
                             const float* __restrict__ compat,
                             float* __restrict__ q) {
    __shared__ float sT[NPHI * 12];
    __shared__ float sC[C * C];
    int t = threadIdx.x;
    for (int k = t; k < NPHI * 12; k += 256) sT[k] = g_T[k];
    if (t < C * C) sC[t] = compat[t];
    __syncthreads();
    int i = blockIdx.x * 256 + t;
    float m[C];
#pragma unroll
    for (int c = 0; c < C; c++) {
        float s = 0.0f;
#pragma unroll
        for (int js = 0; js < JSPLIT; js++)
            s += g_partial[((size_t)js * C + c) * NPTS + i];
        m[c] = s;
    }
    for (int r = 0; r < NPHI; r++) {
        float ph = g_phi[r * NPTS + i];
#pragma unroll
        for (int c = 0; c < C; c++) m[c] = fmaf(sT[r * 12 + c], ph, m[c]);
    }
#pragma unroll
    for (int c = 0; c < C; c++) {
        float acc = unaries[c * NPTS + i];
#pragma unroll
        for (int cc = 0; cc < C; cc++)
            acc = fmaf(-sC[c * C + cc], m[cc], acc);
        q[c * NPTS + i] = acc;
    }
}

extern "C" void kernel_launch(void* const* d_in, const int* in_sizes, int n_in,
                              void* d_out, int out_size) {
    const float* unaries = (const float*)d_in[0];
    const float* feat    = (const float*)d_in[1];
    const float* Ws      = (const float*)d_in[2];
    const float* Wb      = (const float*)d_in[3];
    const float* compat  = (const float*)d_in[4];
    float* q = (float*)d_out;

    prep_feats<<<NPTS / 256, 256>>>(feat);
    prep_phi<<<NPTS / 256, 256>>>(feat);
    zero_gB<<<(NJC * BCH_BYTES / 4 + 255) / 256, 256>>>();
    genK<<<dim3(NT, NT), 128>>>();
    softmax0<<<NPTS / 128, 128>>>(unaries, Ws, Wb);
    T_kernel<<<NPHI, 256>>>();
    gemm_bl<<<dim3(NT, JSPLIT), 128>>>();
    for (int it = 1; it < 5; it++) {
        update<<<NPTS / 256, 256>>>(unaries, compat, Ws, Wb);
        T_kernel<<<NPHI, 256>>>();
        gemm_bl<<<dim3(NT, JSPLIT), 128>>>();
    }
    reduce_final<<<NPTS / 256, 256>>>(unaries, compat, q);
}

// round 16
// speedup vs baseline: 1.9355x; 1.0163x over previous
#include <cuda_runtime.h>
#include <math.h>
#include <stdint.h>

#define NPTS 8192
#define C    10
#define NPHI 84
#define NT   64            // 128-row i tiles
#define NJC  256           // 32-col j chunks
#define KCH_BYTES 4096     // 128x32 int8 K chunk
#define BCH_BYTES 512      // 16x32  int8 B chunk
#define JSPLIT 16
#define NCH (NJC / JSPLIT) // 16 chunks per CTA
#define NSTAGE 4
#define BUF_STRIDE 4608    // 4KB K + 512B B

typedef unsigned long long u64;
typedef unsigned int u32;
typedef unsigned char u8;

// ---- static scratch ----
__device__ __align__(16) float g_prep[NPTS * 8];
__device__ __align__(16) float g_phi[NPHI * NPTS];
__device__ __align__(128) u8  g_K[(size_t)NT * NJC * KCH_BYTES];  // s8 round(K*127), [ti][jc][i128][j32]
__device__ __align__(128) u8  g_B[NJC * BCH_BYTES];               // s8 round(b*127), [jc][c16][j32]
__device__ __align__(16) float g_A[C * NPTS];
__device__ __align__(16) float g_T[NPHI * 12];
__device__ __align__(16) float g_partial[JSPLIT * C * NPTS];

// ---- helpers ----
static __device__ __forceinline__ u64 pack2(float lo, float hi) {
    u64 r; asm("mov.b64 %0,{%1,%2};" : "=l"(r) : "f"(lo), "f"(hi)); return r;
}
static __device__ __forceinline__ void unpack2(u64 v, float& lo, float& hi) {
    asm("mov.b64 {%0,%1},%2;" : "=f"(lo), "=f"(hi) : "l"(v));
}
static __device__ __forceinline__ u64 fma2(u64 a, u64 b, u64 c) {
    u64 d; asm("fma.rn.f32x2 %0,%1,%2,%3;" : "=l"(d) : "l"(a), "l"(b), "l"(c)); return d;
}
static __device__ __forceinline__ u64 mul2(u64 a, u64 b) {
    u64 d; asm("mul.rn.f32x2 %0,%1,%2;" : "=l"(d) : "l"(a), "l"(b)); return d;
}
static __device__ __forceinline__ float ex2(float x) {
    float r; asm("ex2.approx.ftz.f32 %0,%1;" : "=f"(r) : "f"(x)); return r;
}
static __device__ __forceinline__ u32 smem_u32(const void* p) {
    u32 a; asm("{ .reg .u64 t; cvta.to.shared.u64 t, %1; cvt.u32.u64 %0, t; }" : "=r"(a) : "l"(p));
    return a;
}
static __device__ __forceinline__ void cp16(u32 s, const void* g) {
    asm volatile("cp.async.cg.shared.global [%0], [%1], 16;" :: "r"(s), "l"(g) : "memory");
}
#define CP_COMMIT() asm volatile("cp.async.commit_group;" ::: "memory")
#define CP_WAIT(n)  asm volatile("cp.async.wait_group %0;" :: "n"(n) : "memory")

static __device__ __forceinline__ void ldsm_x4(u32& r0, u32& r1, u32& r2, u32& r3, u32 a) {
    asm volatile("ldmatrix.sync.aligned.m8n8.x4.shared.b16 {%0,%1,%2,%3}, [%4];"
        : "=r"(r0), "=r"(r1), "=r"(r2), "=r"(r3) : "r"(a));
}
static __device__ __forceinline__ void ldsm_x2(u32& r0, u32& r1, u32 a) {
    asm volatile("ldmatrix.sync.aligned.m8n8.x2.shared.b16 {%0,%1}, [%2];"
        : "=r"(r0), "=r"(r1) : "r"(a));
}
static __device__ __forceinline__ void mma_s8(int* d, const u32* a, const u32* b) {
    asm volatile("mma.sync.aligned.m16n8k32.row.col.s32.s8.s8.s32 "
        "{%0,%1,%2,%3}, {%4,%5,%6,%7}, {%8,%9}, {%0,%1,%2,%3};"
        : "+r"(d[0]), "+r"(d[1]), "+r"(d[2]), "+r"(d[3])
        : "r"(a[0]), "r"(a[1]), "r"(a[2]), "r"(a[3]), "r"(b[0]), "r"(b[1]));
}

// ============ one-time prep: feats + phi + zero B ============
__global__ void prep_all(const float* __restrict__ feat) {
    int i = blockIdx.x * blockDim.x + threadIdx.x;
    if (i >= NPTS) return;
    // scaled bilateral feats: u = f*sqrt(log2 e); h = |u|^2/2.  K = 2^(u.u' - h - h')
    const float S = 1.2011224087864498f;
    float u[6]; float h = 0.0f;
#pragma unroll
    for (int d = 0; d < 6; d++) { u[d] = feat[d * NPTS + i] * S; h += u[d] * u[d]; }
    h *= 0.5f;
    float* r = g_prep + (size_t)i * 8;
#pragma unroll
    for (int d = 0; d < 6; d++) r[d] = u[d];
    r[6] = h; r[7] = 0.0f;
    // spatial low-rank features
    float s0 = feat[0 * NPTS + i] * 0.125f;
    float s1 = feat[1 * NPTS + i] * 0.125f;
    float s2 = feat[2 * NPTS + i] * 0.125f;
    float E = __expf(-0.5f * (s0 * s0 + s1 * s1 + s2 * s2));
    float fact[7] = {1.f, 1.f, 2.f, 6.f, 24.f, 120.f, 720.f};
    int rr = 0;
    float px = 1.0f;
    for (int ax = 0; ax <= 6; ax++) {
        float py = 1.0f;
        for (int ay = 0; ay <= 6 - ax; ay++) {
            float pz = 1.0f;
            for (int az = 0; az <= 6 - ax - ay; az++) {
                g_phi[rr * NPTS + i] = E * px * py * pz * rsqrtf(fact[ax] * fact[ay] * fact[az]);
                rr++; pz *= s2;
            }
            py *= s1;
        }
        px *= s0;
    }
    // zero g_B (NJC*BCH_BYTES/4 = 32768 words; 8192 threads -> 4 words each)
    u32* bw = (u32*)g_B;
#pragma unroll
    for (int k = 0; k < 4; k++) bw[i + k * NPTS] = 0;
}

// ============ K generator: s8 round(K*127), layout [ti][jc][i 128][j 32] ============
// v3: LDS.128 j-record loads, bank-conflict-free padded stile, coalesced u32 copy-out.
#define STP 9  // padded words per row
__global__ void __launch_bounds__(128) genK() {
    __shared__ __align__(16) float sj[128 * 8];         // 4KB j-features
    __shared__ __align__(16) u32 stile[4 * 128 * STP];  // 18KB padded output tile
    int tid = threadIdx.x, ti = blockIdx.x, tj = blockIdx.y;
    {
        const float4* src = (const float4*)(g_prep + (size_t)tj * 128 * 8);
        float4* dst = (float4*)sj;
        dst[tid] = src[tid];
        dst[tid + 128] = src[tid + 128];
    }
    __syncthreads();
    int i = ti * 128 + tid;
    const u64* ir = (const u64*)(g_prep + (size_t)i * 8);
    u64 a0 = ir[0], a1 = ir[1], a2 = ir[2];
    float hi_, du; unpack2(ir[3], hi_, du);
    float ci = 6.9886846867721655f - hi_;  // log2(127) - h_i : folds *127 into exponent
    const float4* sjf4 = (const float4*)sj;
#pragma unroll 2
    for (int j0 = 0; j0 < 128; j0 += 4) {
        u32 word = 0;
#pragma unroll
        for (int e = 0; e < 4; e++) {
            int j = j0 + e;
            float4 A4 = sjf4[j * 2];       // u0 u1 u2 u3  (LDS.128 broadcast)
            float4 B4 = sjf4[j * 2 + 1];   // u4 u5 h  0
            u64 p01 = pack2(A4.x, A4.y);
            u64 p23 = pack2(A4.z, A4.w);
            u64 p45 = pack2(B4.x, B4.y);
            u64 d = fma2(a0, p01, fma2(a1, p23, mul2(a2, p45)));
            float lo, hh; unpack2(d, lo, hh);
            int v = __float2int_rn(ex2(lo + hh + (ci - B4.z)));  // [0,127]
            word |= ((u32)(v & 0xFF)) << (8 * e);
        }
        // padded: [chunk][row][word], row stride STP=9 -> conflict-free writes
        stile[((j0 >> 5) * 128 * STP) + tid * STP + ((j0 & 31) >> 2)] = word;
    }
    __syncthreads();
    u32* gout = (u32*)(g_K + ((size_t)ti * NJC + (size_t)tj * 4) * KCH_BYTES);
#pragma unroll
    for (int k = 0; k < 32; k++) {
        int gw = tid + k * 128;            // word within 16KB tile
        int cc = gw >> 10;
        int rem = gw & 1023;
        int row = rem >> 3, w = rem & 7;
        gout[gw] = stile[cc * 128 * STP + row * STP + w];
    }
}

// ---- shared softmax->A,B body ----
static __device__ __forceinline__ void softmax_store(const float* v_in, int i,
                                                     const float* sWs, const float* sWb) {
    float v[C];
    float m = -1e30f;
#pragma unroll
    for (int c = 0; c < C; c++) { v[c] = v_in[c]; m = fmaxf(m, v[c]); }
    float s = 0.0f;
#pragma unroll
    for (int c = 0; c < C; c++) { v[c] = __expf(v[c] - m); s += v[c]; }
    float inv = 1.0f / s;
#pragma unroll
    for (int c = 0; c < C; c++) v[c] *= inv;
    u8* bdst = g_B + (size_t)(i >> 5) * BCH_BYTES + (i & 31);
#pragma unroll
    for (int c = 0; c < C; c++) {
        float a = 0.0f, b = 0.0f;
#pragma unroll
        for (int cc = 0; cc < C; cc++) {
            a = fmaf(sWs[c * C + cc], v[cc], a);
            b = fmaf(sWb[c * C + cc], v[cc], b);
        }
        g_A[c * NPTS + i] = a;
        int iv = __float2int_rn(b * 127.0f);
        iv = iv > 127 ? 127 : (iv < -127 ? -127 : iv);
        bdst[c * 32] = (u8)(iv & 0xFF);
    }
}

// iteration 0: softmax of unaries
__global__ void softmax0(const float* __restrict__ unaries,
                         const float* __restrict__ Ws,
                         const float* __restrict__ Wb) {
    __shared__ float sWs[C * C], sWb[C * C];
    int t = threadIdx.x;
    if (t < C * C) { sWs[t] = Ws[t]; sWb[t] = Wb[t]; }
    __syncthreads();
    int i = blockIdx.x * blockDim.x + t;
    if (i >= NPTS) return;
    float v[C];
#pragma unroll
    for (int c = 0; c < C; c++) v[c] = unaries[c * NPTS + i];
    softmax_store(v, i, sWs, sWb);
}

__global__ void T_kernel() {
    int r = blockIdx.x, t = threadIdx.x;
    float acc[C];
#pragma unroll
    for (int c = 0; c < C; c++) acc[c] = 0.0f;
    for (int i = t; i < NPTS; i += 256) {
        float ph = g_phi[r * NPTS + i];
#pragma unroll
        for (int c = 0; c < C; c++) acc[c] = fmaf(g_A[c * NPTS + i], ph, acc[c]);
    }
    __shared__ float s[C][256];
#pragma unroll
    for (int c = 0; c < C; c++) s[c][t] = acc[c];
    __syncthreads();
    for (int w = 128; w > 0; w >>= 1) {
        if (t < w)
#pragma unroll
            for (int c = 0; c < C; c++) s[c][t] += s[c][t + w];
        __syncthreads();
    }
    if (t < C) g_T[r * 12 + t] = s[t][0];
}

// ---- bilateral GEMM via mma.sync s8, cp.async.cg quad-buffered (proven body) ----
__global__ void __launch_bounds__(128) gemm_bl() {
    __shared__ __align__(128) u8 pool[NSTAGE * BUF_STRIDE];
    u32 base = smem_u32(pool);
    int tid = threadIdx.x, w = tid >> 5, l = tid & 31;
    int ti = blockIdx.x, js = blockIdx.y;

    u32 aoff[2], boff[2];
#pragma unroll
    for (int t = 0; t < 2; t++) {
        int m = l >> 3, r = l & 7;
        aoff[t] = (u32)((w * 32 + t * 16 + (m & 1) * 8 + r) * 32 + (m >> 1) * 16);
    }
#pragma unroll
    for (int n = 0; n < 2; n++) {
        int ll = l & 15;
        boff[n] = (u32)(4096 + (n * 8 + (ll & 7)) * 32 + ((ll >> 3) & 1) * 16);
    }

    int acc[2][2][4];
#pragma unroll
    for (int t = 0; t < 2; t++)
#pragma unroll
        for (int n = 0; n < 2; n++)
#pragma unroll
            for (int k = 0; k < 4; k++) acc[t][n][k] = 0;

    int jc0 = js * NCH;
    const u8* ksrc = g_K + ((size_t)ti * NJC + jc0) * KCH_BYTES;
    const u8* bsrc = g_B + (size_t)jc0 * BCH_BYTES;

#pragma unroll
    for (int ch = 0; ch < NSTAGE; ch++) {
        u32 bufb = base + ch * BUF_STRIDE;
        const u8* kp = ksrc + (size_t)ch * KCH_BYTES;
        cp16(bufb + tid * 16, kp + tid * 16);
        cp16(bufb + (tid + 128) * 16, kp + (tid + 128) * 16);
        if (tid < 32) cp16(bufb + 4096 + tid * 16, bsrc + (size_t)ch * BCH_BYTES + tid * 16);
        CP_COMMIT();
    }

#pragma unroll 4
    for (int ch = 0; ch < NCH; ch++) {
        CP_WAIT(NSTAGE - 1);
        __syncthreads();
        u32 bufb = base + (ch % NSTAGE) * BUF_STRIDE;
        u32 afrag[2][4]; u32 bfrag[2][2];
#pragma unroll
        for (int t = 0; t < 2; t++)
            ldsm_x4(afrag[t][0], afrag[t][1], afrag[t][2], afrag[t][3], bufb + aoff[t]);
#pragma unroll
        for (int n = 0; n < 2; n++)
            ldsm_x2(bfrag[n][0], bfrag[n][1], bufb + boff[n]);
#pragma unroll
        for (int t = 0; t < 2; t++)
#pragma unroll
            for (int n = 0; n < 2; n++)
                mma_s8(acc[t][n], afrag[t], bfrag[n]);
        __syncthreads();
        int nch = ch + NSTAGE;
        if (nch < NCH) {
            const u8* kp = ksrc + (size_t)nch * KCH_BYTES;
            cp16(bufb + tid * 16, kp + tid * 16);
            cp16(bufb + (tid + 128) * 16, kp + (tid + 128) * 16);
            if (tid < 32) cp16(bufb + 4096 + tid * 16, bsrc + (size_t)nch * BCH_BYTES + tid * 16);
        }
        CP_COMMIT();
    }
    CP_WAIT(0);

    const float sc = 1.0f / 16129.0f;  // 1/(127*127)
    float* P = g_partial + (size_t)js * C * NPTS;
#pragma unroll
    for (int t = 0; t < 2; t++) {
        int row0 = ti * 128 + w * 32 + t * 16 + (l >> 2);
#pragma unroll
        for (int n = 0; n < 2; n++) {
            int c0 = n * 8 + 2 * (l & 3);
#pragma unroll
            for (int h = 0; h < 2; h++) {
                int row = row0 + h * 8;
                if (c0 < C)     P[c0 * NPTS + row]       = (float)acc[t][n][h * 2 + 0] * sc;
                if (c0 + 1 < C) P[(c0 + 1) * NPTS + row] = (float)acc[t][n][h * 2 + 1] * sc;
            }
        }
    }
}

// ---- fused message-combine + q + softmax + A/B (iterations 1..4) ----
__global__ void update(const float* __restrict__ unaries,
                       const float* __restrict__ compat,
                       const float* __restrict__ Ws,
                       const float* __restrict__ Wb) {
    __shared__ float sT[NPHI * 12];
    __shared__ float sC[C * C], sWs[C * C], sWb[C * C];
    int t = threadIdx.x;
    for (int k = t; k < NPHI * 12; k += 256) sT[k] = g_T[k];
    if (t < C * C) { sC[t] = compat[t]; sWs[t] = Ws[t]; sWb[t] = Wb[t]; }
    __syncthreads();
    int i = blockIdx.x * 256 + t;
    float m[C];
#pragma unroll
    for (int c = 0; c < C; c++) {
        float s = 0.0f;
#pragma unroll
        for (int js = 0; js < JSPLIT; js++)
            s += g_partial[((size_t)js * C + c) * NPTS + i];
        m[c] = s;
    }
    for (int r = 0; r < NPHI; r++) {
        float ph = g_phi[r * NPTS + i];
#pragma unroll
        for (int c = 0; c < C; c++) m[c] = fmaf(sT[r * 12 + c], ph, m[c]);
    }
    float qv[C];
#pragma unroll
    for (int c = 0; c < C; c++) {
        float acc = unaries[c * NPTS + i];
#pragma unroll
        for (int cc = 0; cc < C; cc++)
            acc = fmaf(-sC[c * C + cc], m[cc], acc);
        qv[c] = acc;
    }
    softmax_store(qv, i, sWs, sWb);
}

// ---- final combine -> q written to d_out ----
__global__ void reduce_final(const float* __restrict__ unaries,
                             const float* __restrict__ compat,
                             float* __restrict__ q) {
    __shared__ float sT[NPHI * 12];
    __shared__ float sC[C * C];
    int t = threadIdx.x;
    for (int k = t; k < NPHI * 12; k += 256) sT[k] = g_T[k];
    if (t < C * C) sC[t] = compat[t];
    __syncthreads();
    int i = blockIdx.x * 256 + t;
    float m[C];
#pragma unroll
    for (int c = 0; c < C; c++) {
        float s = 0.0f;
#pragma unroll
        for (int js = 0; js < JSPLIT; js++)
            s += g_partial[((size_t)js * C + c) * NPTS + i];
        m[c] = s;
    }
    for (int r = 0; r < NPHI; r++) {
        float ph = g_phi[r * NPTS + i];
#pragma unroll
        for (int c = 0; c < C; c++) m[c] = fmaf(sT[r * 12 + c], ph, m[c]);
    }
#pragma unroll
    for (int c = 0; c < C; c++) {
        float acc = unaries[c * NPTS + i];
#pragma unroll
        for (int cc = 0; cc < C; cc++)
            acc = fmaf(-sC[c * C + cc], m[cc], acc);
        q[c * NPTS + i] = acc;
    }
}

extern "C" void kernel_launch(void* const* d_in, const int* in_sizes, int n_in,
                              void* d_out, int out_size) {
    const float* unaries = (const float*)d_in[0];
    const float* feat    = (const float*)d_in[1];
    const float* Ws      = (const float*)d_in[2];
    const float* Wb      = (const float*)d_in[3];
    const float* compat  = (const float*)d_in[4];
    float* q = (float*)d_out;

    prep_all<<<NPTS / 256, 256>>>(feat);
    genK<<<dim3(NT, NT), 128>>>();
    softmax0<<<NPTS / 128, 128>>>(unaries, Ws, Wb);
    T_kernel<<<NPHI, 256>>>();
    gemm_bl<<<dim3(NT, JSPLIT), 128>>>();
    for (int it = 1; it < 5; it++) {
        update<<<NPTS / 256, 256>>>(unaries, compat, Ws, Wb);
        T_kernel<<<NPHI, 256>>>();
        gemm_bl<<<dim3(NT, JSPLIT), 128>>>();
    }
    reduce_final<<<NPTS / 256, 256>>>(unaries, compat, q);
}